// round 4
// baseline (speedup 1.0000x reference)
#include <cuda_runtime.h>
#include <cuda_bf16.h>

// Problem constants (fixed shapes per reference)
#define N_NODES  100000
#define E_EDGES  1000000
#define IN_F     64
#define OUT_F    64
#define N_REL    16
#define N_BASES  8

#define CHUNK    2048
#define NCHUNKS  ((E_EDGES + CHUNK - 1) / CHUNK)   // 489
#define BATCH    6
#define NC       27        // K3 column-segments per relation (27*16=432 CTAs < 148*3)

// ---------------------------------------------------------------------------
// Device scratch (static allocation only — no cudaMalloc allowed)
// ---------------------------------------------------------------------------
// Basis-combined relation weights, stored in 2x2-block layout for direct
// f32x2 consumption:
//   float quad at d_W[r*4096 + (j*32+l)*4 + c]:
//     c=0: W[r][2j  ][2l  ]   c=1: W[r][2j+1][2l  ]
//     c=2: W[r][2j  ][2l+1]   c=3: W[r][2j+1][2l+1]
// so ulonglong2 Wq = .x = {W[2j][2l],   W[2j+1][2l]}
//                    .y = {W[2j][2l+1], W[2j+1][2l+1]}
__device__ float d_W[N_REL * IN_F * OUT_F];
__device__ int   d_cnt[N_REL];
__device__ int   d_off[N_REL];
__device__ int   d_cur[N_REL];
__device__ int2  d_se[E_EDGES];     // edges sorted by relation: {src, dst}

// ---------------------------------------------------------------------------
// K1: basis combination (with the reference's reinterpreting-reshape quirk),
//     written directly into the 2x2-block layout. Also zeros d_cnt.
//     Effective W[r,k,o] = M_flat[r*4096 + k*64 + o] where
//     M_flat[i*1024 + rm*64 + om] = sum_b w_comp[rm,b] * weight[i*512+b*64+om]
// ---------------------------------------------------------------------------
__global__ void compute_W_kernel(const float* __restrict__ weight,
                                 const float* __restrict__ w_comp) {
    int idx = blockIdx.x * blockDim.x + threadIdx.x;
    if (blockIdx.x == 0 && threadIdx.x < N_REL) d_cnt[threadIdx.x] = 0;
    if (idx >= N_REL * IN_F * OUT_F) return;
    int r  = idx >> 12;
    int j  = (idx >> 7) & 31;
    int l  = (idx >> 2) & 31;
    int c2 = idx & 3;
    int k  = 2 * j + (c2 & 1);
    int o  = 2 * l + (c2 >> 1);
    int t  = r * 4096 + k * 64 + o;     // W-flat index
    int im = t >> 10;                   // reinterpret as M-flat
    int rm = (t >> 6) & 15;
    int om = t & 63;
    float s = 0.f;
#pragma unroll
    for (int b = 0; b < N_BASES; b++)
        s += w_comp[rm * N_BASES + b] * weight[im * 512 + b * 64 + om];
    d_W[idx] = s;
}

// ---------------------------------------------------------------------------
// K_hist: per-chunk smem histogram of rel, accumulated into d_cnt.
// ---------------------------------------------------------------------------
__global__ void hist_kernel(const int* __restrict__ rel) {
    __shared__ int hc[N_REL];
    int tid = threadIdx.x;
    if (tid < N_REL) hc[tid] = 0;
    __syncthreads();
    int base = blockIdx.x * CHUNK;
#pragma unroll 2
    for (int j = tid; j < CHUNK; j += 256) {
        int e = base + j;
        if (e < E_EDGES) atomicAdd(&hc[rel[e]], 1);
    }
    __syncthreads();
    if (tid < N_REL) atomicAdd(&d_cnt[tid], hc[tid]);
}

// ---------------------------------------------------------------------------
// K_scan: exclusive scan of the 16 counts -> d_off, d_cur.  One warp.
// ---------------------------------------------------------------------------
__global__ void scan_kernel() {
    int t = threadIdx.x;
    int c = (t < N_REL) ? d_cnt[t] : 0;
    int v = c;
#pragma unroll
    for (int d = 1; d < N_REL; d <<= 1) {
        int u = __shfl_up_sync(0xffffffffu, v, d);
        if (t >= d) v += u;
    }
    if (t < N_REL) {
        int excl = v - c;
        d_off[t] = excl;
        d_cur[t] = excl;
    }
}

// ---------------------------------------------------------------------------
// K_sort: counting-sort scatter.  Each CTA: local histogram of its chunk,
// reserve global ranges via atomicAdd on d_cur, then scatter {src,dst}.
// ---------------------------------------------------------------------------
__global__ void sort_kernel(const int* __restrict__ src,
                            const int* __restrict__ dst,
                            const int* __restrict__ rel) {
    __shared__ int hc[N_REL];
    int tid = threadIdx.x;
    if (tid < N_REL) hc[tid] = 0;
    __syncthreads();
    int base = blockIdx.x * CHUNK;
#pragma unroll 2
    for (int j = tid; j < CHUNK; j += 256) {
        int e = base + j;
        if (e < E_EDGES) atomicAdd(&hc[rel[e]], 1);
    }
    __syncthreads();
    if (tid < N_REL) hc[tid] = atomicAdd(&d_cur[tid], hc[tid]);
    __syncthreads();
#pragma unroll 2
    for (int j = tid; j < CHUNK; j += 256) {
        int e = base + j;
        if (e < E_EDGES) {
            int p = atomicAdd(&hc[rel[e]], 1);
            d_se[p] = make_int2(src[e], dst[e]);
        }
    }
}

// ---------------------------------------------------------------------------
// K2: h_new = relu(h) into out[0 : N*64), zero out[N*64 : 2*N*64)
// ---------------------------------------------------------------------------
__global__ void relu_zero_kernel(const float4* __restrict__ h, float4* out) {
    int i = blockIdx.x * blockDim.x + threadIdx.x;
    const int n4 = N_NODES * IN_F / 4;
    if (i >= n4) return;
    float4 v = h[i];
    v.x = fmaxf(v.x, 0.f);
    v.y = fmaxf(v.y, 0.f);
    v.z = fmaxf(v.z, 0.f);
    v.w = fmaxf(v.w, 0.f);
    out[i] = v;
    out[n4 + i] = make_float4(0.f, 0.f, 0.f, 0.f);
}

// ---------------------------------------------------------------------------
// K3: sorted-edge message + scatter.  grid = (NC_part, 16).
//   CTA (c, r): W[r] in SMEM (2x2-block layout), process segment c of
//   relation r's sorted edges.  Warps take BATCH edges at a time:
//     - h operand pairs {h[2j],h[2j+1]} loaded as packed b64 via uniform
//       LDG.128 (no packs, no shuffles)
//     - one LDS.128 per k-pair delivers the 2x2 weight block per lane
//     - fma.rn.f32x2 into even/odd-output accumulators
//     - out[2l] = accE.lo + accE.hi, scatter via red.global.add.v2.f32
// ---------------------------------------------------------------------------
__global__ void __launch_bounds__(256, 3)
scatter_msg_kernel(const ulonglong2* __restrict__ h2v,
                   float* __restrict__ h2,
                   int c_base) {
    __shared__ ulonglong2 Wq[32 * 32];   // 16 KB

    const int r = blockIdx.y;
    const int c = c_base + blockIdx.x;
    const int start = d_off[r];
    const int cnt   = d_cnt[r];
    const int seg   = (cnt + NC - 1) / NC;
    const int s0    = start + c * seg;
    const int s1    = min(start + cnt, s0 + seg);
    if (s0 >= s1) return;

    const int tid = threadIdx.x;
    // Load W[r] into SMEM.
    {
        const ulonglong2* Wg = (const ulonglong2*)d_W + r * 1024;
#pragma unroll
        for (int i2 = tid; i2 < 1024; i2 += 256) Wq[i2] = Wg[i2];
    }
    __syncthreads();

    const int wid  = tid >> 5;
    const int lane = tid & 31;

    for (int gb = s0 + wid * BATCH; gb < s1; gb += 8 * BATCH) {
        const int m = min(BATCH, s1 - gb);

        // Uniform loads of sorted {src,dst}; same value in all lanes.
        const ulonglong2* pe[BATCH];
#pragma unroll
        for (int e = 0; e < BATCH; e++) {
            int se = (e < m) ? __ldg(&d_se[gb + e].x) : 0;
            pe[e] = h2v + (long)se * 16;     // 64 floats = 16 x 16B per row
        }

        unsigned long long accE[BATCH], accO[BATCH];
#pragma unroll
        for (int e = 0; e < BATCH; e++) { accE[e] = 0ull; accO[e] = 0ull; }

#pragma unroll
        for (int jj = 0; jj < 16; jj++) {
            ulonglong2 hp[BATCH];
#pragma unroll
            for (int e = 0; e < BATCH; e++)
                hp[e] = __ldg(pe[e] + jj);   // .x={h[4jj],h[4jj+1]} .y={h[4jj+2],h[4jj+3]}
            ulonglong2 w0 = Wq[(2 * jj) * 32 + lane];
            ulonglong2 w1 = Wq[(2 * jj + 1) * 32 + lane];
#pragma unroll
            for (int e = 0; e < BATCH; e++) {
                asm("fma.rn.f32x2 %0, %1, %2, %0;" : "+l"(accE[e]) : "l"(hp[e].x), "l"(w0.x));
                asm("fma.rn.f32x2 %0, %1, %2, %0;" : "+l"(accO[e]) : "l"(hp[e].x), "l"(w0.y));
                asm("fma.rn.f32x2 %0, %1, %2, %0;" : "+l"(accE[e]) : "l"(hp[e].y), "l"(w1.x));
                asm("fma.rn.f32x2 %0, %1, %2, %0;" : "+l"(accO[e]) : "l"(hp[e].y), "l"(w1.y));
            }
        }

        // Scatter: out[2l] = accE.lo+accE.hi ; out[2l+1] = accO.lo+accO.hi
#pragma unroll
        for (int e = 0; e < BATCH; e++) {
            if (e < m) {
                int de = __ldg(&d_se[gb + e].y);
                float e0, e1, o0, o1;
                asm("mov.b64 {%0, %1}, %2;" : "=f"(e0), "=f"(e1) : "l"(accE[e]));
                asm("mov.b64 {%0, %1}, %2;" : "=f"(o0), "=f"(o1) : "l"(accO[e]));
                float ax = e0 + e1;
                float ay = o0 + o1;
                float* p = h2 + (long)de * 64 + 2 * lane;
                asm volatile("red.global.add.v2.f32 [%0], {%1, %2};"
                             :: "l"(p), "f"(ax), "f"(ay) : "memory");
            }
        }
    }
}

// ---------------------------------------------------------------------------
extern "C" void kernel_launch(void* const* d_in, const int* in_sizes, int n_in,
                              void* d_out, int out_size) {
    const float* h      = (const float*)d_in[0];
    const float* weight = (const float*)d_in[1];
    const float* w_comp = (const float*)d_in[2];
    const int*   src    = (const int*)d_in[3];
    const int*   dst    = (const int*)d_in[4];
    const int*   rel    = (const int*)d_in[5];
    float* out = (float*)d_out;          // [h_new (N*64) | h2 (N*64)]
    float* h2  = out + N_NODES * IN_F;

    // K1: basis combination into 2x2-block d_W (+ zero d_cnt)
    compute_W_kernel<<<(N_REL * IN_F * OUT_F + 255) / 256, 256>>>(weight, w_comp);

    // Counting sort by relation
    hist_kernel<<<NCHUNKS, 256>>>(rel);
    scan_kernel<<<1, 32>>>();
    sort_kernel<<<NCHUNKS, 256>>>(src, dst, rel);

    // K2: relu(h) -> out, zero h2
    relu_zero_kernel<<<(N_NODES * IN_F / 4 + 255) / 256, 256>>>(
        (const float4*)h, (float4*)out);

    // K3: edge messages + scatter (split so the ncu capture slot lands here)
    dim3 gridA(14, N_REL);
    dim3 gridB(NC - 14, N_REL);
    scatter_msg_kernel<<<gridA, 256>>>((const ulonglong2*)h, h2, 0);
    scatter_msg_kernel<<<gridB, 256>>>((const ulonglong2*)h, h2, 14);
}